// round 1
// baseline (speedup 1.0000x reference)
#include <cuda_runtime.h>
#include <math.h>

// Scratch for Q, K, V projections: [N=8, C=1024, W=1024] fp32 each.
__device__ float g_q[8u * 1024u * 1024u];
__device__ float g_k[8u * 1024u * 1024u];
__device__ float g_v[8u * 1024u * 1024u];

// ---------------------------------------------------------------------------
// QKV projection: for batch n, out[o,w] = sum_c W[o,c] * hs[n,c,w] + b[o]
// Classic 128x128x8 register-tiled SGEMM, 256 threads, 8x8 per thread.
// grid: (W/128=8, O/128=8, N*3=24); z selects (n, which of q/k/v)
// ---------------------------------------------------------------------------
__global__ __launch_bounds__(256) void qkv_gemm_kernel(
    const float* __restrict__ hs,
    const float* __restrict__ wq, const float* __restrict__ bq,
    const float* __restrict__ wk, const float* __restrict__ bk,
    const float* __restrict__ wv, const float* __restrict__ bv)
{
    const int which = blockIdx.z % 3;
    const int n     = blockIdx.z / 3;

    const float* A;
    const float* bias;
    float* out;
    if (which == 0)      { A = wq; bias = bq; out = g_q; }
    else if (which == 1) { A = wk; bias = bk; out = g_k; }
    else                 { A = wv; bias = bv; out = g_v; }

    const float* B = hs + (size_t)n * 1024u * 1024u;
    out += (size_t)n * 1024u * 1024u;

    const int m0 = blockIdx.y * 128;
    const int w0 = blockIdx.x * 128;

    __shared__ float As[8][128];
    __shared__ float Bs[8][128];

    const int t  = threadIdx.x;
    const int tx = t & 15;        // 0..15  -> output cols
    const int ty = t >> 4;        // 0..15  -> output rows

    // A tile load mapping: 128 rows x 8 cols = 256 float4 (1 per thread)
    const int arow = t >> 1;            // 0..127
    const int ac4  = (t & 1) * 4;       // 0 or 4
    // B tile load mapping: 8 rows x 128 cols = 256 float4
    const int brow = t >> 5;            // 0..7
    const int bc4  = (t & 31) * 4;      // 0..124

    float acc[8][8];
#pragma unroll
    for (int i = 0; i < 8; i++)
#pragma unroll
        for (int j = 0; j < 8; j++) acc[i][j] = 0.f;

    for (int k0 = 0; k0 < 1024; k0 += 8) {
        float4 av = *(const float4*)&A[(size_t)(m0 + arow) * 1024 + k0 + ac4];
        float4 bv4 = *(const float4*)&B[(size_t)(k0 + brow) * 1024 + w0 + bc4];

        __syncthreads();   // previous iteration's compute done
        As[ac4 + 0][arow] = av.x;
        As[ac4 + 1][arow] = av.y;
        As[ac4 + 2][arow] = av.z;
        As[ac4 + 3][arow] = av.w;
        *(float4*)&Bs[brow][bc4] = bv4;
        __syncthreads();

#pragma unroll
        for (int kk = 0; kk < 8; kk++) {
            float a[8], b[8];
            *(float4*)&a[0] = *(const float4*)&As[kk][ty * 4];
            *(float4*)&a[4] = *(const float4*)&As[kk][64 + ty * 4];
            *(float4*)&b[0] = *(const float4*)&Bs[kk][tx * 4];
            *(float4*)&b[4] = *(const float4*)&Bs[kk][64 + tx * 4];
#pragma unroll
            for (int i = 0; i < 8; i++)
#pragma unroll
                for (int j = 0; j < 8; j++)
                    acc[i][j] += a[i] * b[j];
        }
    }

#pragma unroll
    for (int i = 0; i < 8; i++) {
        const int rr = (i < 4) ? (ty * 4 + i) : (64 + ty * 4 + (i - 4));
        const float bb = bias[m0 + rr];
        float4 o0, o1;
        o0.x = acc[i][0] + bb; o0.y = acc[i][1] + bb;
        o0.z = acc[i][2] + bb; o0.w = acc[i][3] + bb;
        o1.x = acc[i][4] + bb; o1.y = acc[i][5] + bb;
        o1.z = acc[i][6] + bb; o1.w = acc[i][7] + bb;
        *(float4*)&out[(size_t)(m0 + rr) * 1024 + w0 + tx * 4]      = o0;
        *(float4*)&out[(size_t)(m0 + rr) * 1024 + w0 + 64 + tx * 4] = o1;
    }
}

// ---------------------------------------------------------------------------
// Flash attention over one (n, h, 64-query tile).
// Q/K/V layout: [N, C=H*D, W] with channel c = h*64+d, positions contiguous.
// scores[q,k] = (1/8) * sum_d Q[d,q]*K[d,k] + mask[n,k]; softmax over k;
// ctx[q,d] = sum_k P[q,k]*V[d,k];  out[n, h*64+d, q] = ctx.
// 256 threads = 16x16, 4x4 micro-tiles. 48KB static smem.
// ---------------------------------------------------------------------------
__global__ __launch_bounds__(256) void attn_kernel(
    const float* __restrict__ mask, float* __restrict__ out)
{
    const int qt = blockIdx.x;   // 0..15
    const int h  = blockIdx.y;   // 0..15
    const int n  = blockIdx.z;   // 0..7

    const int tid = threadIdx.x;
    const int tx  = tid & 15;
    const int ty  = tid >> 4;

    const size_t base = ((size_t)n * 1024 + (size_t)h * 64) * 1024;
    const float* Qh = g_q + base;
    const float* Kh = g_k + base;
    const float* Vh = g_v + base;
    const int q0 = qt * 64;

    __shared__ float Qs[64 * 64];   // [d][q]
    __shared__ float KP[64 * 64];   // first K tile [d][k], then P tile [q][k]
    __shared__ float Vt[64 * 64];   // [k][d] XOR-swizzled: col4 = (d>>2) ^ (k>>2)

    // Load Q tile: Qs[d][q]
#pragma unroll
    for (int it = 0; it < 4; it++) {
        int id = it * 256 + tid;
        int d = id >> 4, q4 = (id & 15) << 2;
        *(float4*)&Qs[d * 64 + q4] = *(const float4*)&Qh[(size_t)d * 1024 + q0 + q4];
    }

    float acc[4][4];
    float mrow[4], lrow[4];
#pragma unroll
    for (int i = 0; i < 4; i++) {
        mrow[i] = -1e30f; lrow[i] = 0.f;
#pragma unroll
        for (int j = 0; j < 4; j++) acc[i][j] = 0.f;
    }

    for (int k0 = 0; k0 < 1024; k0 += 64) {
        __syncthreads();   // prior PV reads of KP/Vt finished
        // Load K tile -> KP[d][k]; V tile -> Vt swizzled [k][d]
#pragma unroll
        for (int it = 0; it < 4; it++) {
            int id = it * 256 + tid;
            int d = id >> 4, k4 = id & 15;
            *(float4*)&KP[d * 64 + (k4 << 2)] =
                *(const float4*)&Kh[(size_t)d * 1024 + k0 + (k4 << 2)];
            float4 v = *(const float4*)&Vh[(size_t)d * 1024 + k0 + (k4 << 2)];
            int c = ((((d >> 2) ^ k4) << 2) | (d & 3));
            Vt[(k4 * 4 + 0) * 64 + c] = v.x;
            Vt[(k4 * 4 + 1) * 64 + c] = v.y;
            Vt[(k4 * 4 + 2) * 64 + c] = v.z;
            Vt[(k4 * 4 + 3) * 64 + c] = v.w;
        }
        float mk[4];
#pragma unroll
        for (int j = 0; j < 4; j++)
            mk[j] = mask[(size_t)n * 1024 + k0 + tx * 4 + j];
        __syncthreads();

        // S = Q^T K  (s[i][j]: q = ty*4+i, k = tx*4+j)
        float s[4][4];
#pragma unroll
        for (int i = 0; i < 4; i++)
#pragma unroll
            for (int j = 0; j < 4; j++) s[i][j] = 0.f;
#pragma unroll
        for (int d = 0; d < 64; d++) {
            float qa[4], kb[4];
            *(float4*)qa = *(const float4*)&Qs[d * 64 + ty * 4];
            *(float4*)kb = *(const float4*)&KP[d * 64 + tx * 4];
#pragma unroll
            for (int i = 0; i < 4; i++)
#pragma unroll
                for (int j = 0; j < 4; j++)
                    s[i][j] += qa[i] * kb[j];
        }

        // Scale + mask + online softmax (row groups of 16 lanes share ty)
#pragma unroll
        for (int i = 0; i < 4; i++) {
#pragma unroll
            for (int j = 0; j < 4; j++) s[i][j] = s[i][j] * 0.125f + mk[j];
            float mt = fmaxf(fmaxf(s[i][0], s[i][1]), fmaxf(s[i][2], s[i][3]));
#pragma unroll
            for (int off = 8; off >= 1; off >>= 1)
                mt = fmaxf(mt, __shfl_xor_sync(0xffffffffu, mt, off));
            float mnew = fmaxf(mrow[i], mt);
            float alpha = __expf(mrow[i] - mnew);
            float rs = 0.f;
#pragma unroll
            for (int j = 0; j < 4; j++) {
                s[i][j] = __expf(s[i][j] - mnew);
                rs += s[i][j];
            }
#pragma unroll
            for (int off = 8; off >= 1; off >>= 1)
                rs += __shfl_xor_sync(0xffffffffu, rs, off);
            lrow[i] = lrow[i] * alpha + rs;
            mrow[i] = mnew;
#pragma unroll
            for (int j = 0; j < 4; j++) acc[i][j] *= alpha;
        }

        __syncthreads();   // everyone done reading KP as K
        // Store P into KP as [q][k]
#pragma unroll
        for (int i = 0; i < 4; i++) {
            float4 p4;
            p4.x = s[i][0]; p4.y = s[i][1]; p4.z = s[i][2]; p4.w = s[i][3];
            *(float4*)&KP[(ty * 4 + i) * 64 + tx * 4] = p4;
        }
        __syncthreads();

        // acc[q][d] += sum_k P[q][k] * V[d][k]   (d = tx*4+j via swizzled Vt)
#pragma unroll
        for (int kk = 0; kk < 64; kk++) {
            float pa[4], vb[4];
#pragma unroll
            for (int i = 0; i < 4; i++) pa[i] = KP[(ty * 4 + i) * 64 + kk];
            *(float4*)vb = *(const float4*)&Vt[kk * 64 + ((tx ^ (kk >> 2)) << 2)];
#pragma unroll
            for (int i = 0; i < 4; i++)
#pragma unroll
                for (int j = 0; j < 4; j++)
                    acc[i][j] += pa[i] * vb[j];
        }
    }

    // Epilogue: normalize, transpose through smem (reuse Qs as [d][q]), store.
    __syncthreads();
#pragma unroll
    for (int i = 0; i < 4; i++) {
        float inv = 1.f / lrow[i];
#pragma unroll
        for (int j = 0; j < 4; j++)
            Qs[(tx * 4 + j) * 64 + ty * 4 + i] = acc[i][j] * inv;
    }
    __syncthreads();
    float* Oh = out + base;
#pragma unroll
    for (int it = 0; it < 4; it++) {
        int id = it * 256 + tid;
        int d = id >> 4, q4 = (id & 15) << 2;
        *(float4*)&Oh[(size_t)d * 1024 + q0 + q4] = *(const float4*)&Qs[d * 64 + q4];
    }
}

extern "C" void kernel_launch(void* const* d_in, const int* in_sizes, int n_in,
                              void* d_out, int out_size)
{
    (void)in_sizes; (void)n_in; (void)out_size;
    const float* hs   = (const float*)d_in[0];
    const float* mask = (const float*)d_in[1];
    const float* wq   = (const float*)d_in[2];
    const float* bq   = (const float*)d_in[3];
    const float* wk   = (const float*)d_in[4];
    const float* bk   = (const float*)d_in[5];
    const float* wv   = (const float*)d_in[6];
    const float* bv   = (const float*)d_in[7];
    float* out = (float*)d_out;

    dim3 g1(8, 8, 24);   // (W/128, O/128, N*3)
    qkv_gemm_kernel<<<g1, 256>>>(hs, wq, bq, wk, bk, wv, bv);

    dim3 g2(16, 16, 8);  // (W/64, H, N)
    attn_kernel<<<g2, 256>>>(mask, out);
}

// round 5
// speedup vs baseline: 1.5900x; 1.5900x over previous
#include <cuda_runtime.h>
#include <cstdint>
#include <math.h>

// Scratch for Q, K, V projections: [N=8, C=1024, W=1024] fp32 each.
__device__ float g_q[8u * 1024u * 1024u];
__device__ float g_k[8u * 1024u * 1024u];
__device__ float g_v[8u * 1024u * 1024u];

// fp32 -> tf32 (round to nearest) returning the b32 bit pattern
__device__ __forceinline__ uint32_t f2tf32(float f) {
    uint32_t u;
    asm("cvt.rna.tf32.f32 %0, %1;" : "=r"(u) : "f"(f));
    return u;
}

// D(m16n8) += A(m16k8) * B(k8n8), tf32 inputs, fp32 accumulate
__device__ __forceinline__ void mma_tf32_16x8x8(
    float* d, const uint32_t* a, const uint32_t* b)
{
    asm volatile(
        "mma.sync.aligned.m16n8k8.row.col.f32.tf32.tf32.f32 "
        "{%0,%1,%2,%3}, {%4,%5,%6,%7}, {%8,%9}, {%0,%1,%2,%3};"
        : "+f"(d[0]), "+f"(d[1]), "+f"(d[2]), "+f"(d[3])
        : "r"(a[0]), "r"(a[1]), "r"(a[2]), "r"(a[3]),
          "r"(b[0]), "r"(b[1]));
}

// ---------------------------------------------------------------------------
// QKV projection on tensor cores (tf32 mma.sync):
//   out[o, w] = sum_c W[o,c] * hs[n,c,w] + b[o]
// CTA tile M=128 (o) x N=128 (w), K in 64 chunks of 16.
// 128 threads = 4 warps (2x2); warp tile 64x64 = 4(m) x 8(n) m16n8k8 tiles.
// A smem [128][16] stride 20 (conflict-free frag reads);
// B smem [16][128] stride 136 (conflict-free frag reads).
// grid: (W/128=8, O/128=8, N*3=24)
// ---------------------------------------------------------------------------
__global__ __launch_bounds__(128) void qkv_gemm_tc(
    const float* __restrict__ hs,
    const float* __restrict__ wq, const float* __restrict__ bq,
    const float* __restrict__ wk, const float* __restrict__ bk,
    const float* __restrict__ wv, const float* __restrict__ bv)
{
    __shared__ uint32_t As[128 * 20];   // 10.0 KB
    __shared__ uint32_t Bs[16 * 136];   //  8.5 KB

    const int which = blockIdx.z % 3;
    const int n     = blockIdx.z / 3;

    const float* A;
    const float* bias;
    float* out;
    if (which == 0)      { A = wq; bias = bq; out = g_q; }
    else if (which == 1) { A = wk; bias = bk; out = g_k; }
    else                 { A = wv; bias = bv; out = g_v; }

    const float* B = hs + (size_t)n * 1024u * 1024u;
    out += (size_t)n * 1024u * 1024u;

    const int m0 = blockIdx.y * 128;
    const int w0 = blockIdx.x * 128;

    const int tid = threadIdx.x;
    const int wid = tid >> 5;
    const int lane = tid & 31;
    const int gid = lane >> 2;   // group id (0..7)
    const int tig = lane & 3;    // thread in group (0..3)
    const int wm = wid >> 1;     // warp m index (0..1)
    const int wn = wid & 1;      // warp n index (0..1)

    // Global load mappings (per chunk; 512 float4 each for A and B)
    // A: idx = it*128+tid: r = idx>>2 (row 0..127), j = idx&3 (float4 col)
    const int a_r = tid >> 2;
    const int a_j = tid & 3;
    // B: k = idx>>5 (0..15), n4 = idx&31
    const int b_k = tid >> 5;    // +4*it
    const int b_n4 = tid & 31;

    const float* gA = A + (size_t)(m0 + a_r) * 1024 + a_j * 4;
    const float* gB = B + (size_t)b_k * 1024 + w0 + b_n4 * 4;

    float acc[4][8][4];
#pragma unroll
    for (int i = 0; i < 4; i++)
#pragma unroll
        for (int j = 0; j < 8; j++)
#pragma unroll
            for (int u = 0; u < 4; u++) acc[i][j][u] = 0.f;

    float4 areg[4], breg[4];

    // Prologue: load chunk 0
#pragma unroll
    for (int it = 0; it < 4; it++) {
        areg[it] = *(const float4*)(gA + (size_t)(it * 32) * 1024);   // rows r+32*it
        breg[it] = *(const float4*)(gB + (size_t)(it * 4) * 1024);    // k rows b_k+4*it
    }

    for (int c = 0; c < 64; c++) {
        // Store staged chunk to smem (with tf32 rounding)
#pragma unroll
        for (int it = 0; it < 4; it++) {
            uint4 ca;
            ca.x = f2tf32(areg[it].x); ca.y = f2tf32(areg[it].y);
            ca.z = f2tf32(areg[it].z); ca.w = f2tf32(areg[it].w);
            *(uint4*)&As[(a_r + it * 32) * 20 + a_j * 4] = ca;
            uint4 cb;
            cb.x = f2tf32(breg[it].x); cb.y = f2tf32(breg[it].y);
            cb.z = f2tf32(breg[it].z); cb.w = f2tf32(breg[it].w);
            *(uint4*)&Bs[(b_k + it * 4) * 136 + b_n4 * 4] = cb;
        }
        __syncthreads();

        // Issue global loads for next chunk (latency hidden by compute below)
        if (c < 63) {
            const int k0 = (c + 1) * 16;
#pragma unroll
            for (int it = 0; it < 4; it++) {
                areg[it] = *(const float4*)(gA + (size_t)(it * 32) * 1024 + k0);
                breg[it] = *(const float4*)(gB + (size_t)(k0 + it * 4) * 1024);
            }
        }

        // Compute: 2 k-steps of 8
#pragma unroll
        for (int t = 0; t < 2; t++) {
            uint32_t af[4][4];
#pragma unroll
            for (int i = 0; i < 4; i++) {
                const int bm = wm * 64 + i * 16;
                af[i][0] = As[(bm + gid) * 20 + t * 8 + tig];
                af[i][1] = As[(bm + gid + 8) * 20 + t * 8 + tig];
                af[i][2] = As[(bm + gid) * 20 + t * 8 + tig + 4];
                af[i][3] = As[(bm + gid + 8) * 20 + t * 8 + tig + 4];
            }
            uint32_t bf[8][2];
#pragma unroll
            for (int j = 0; j < 8; j++) {
                const int bn = wn * 64 + j * 8 + gid;
                bf[j][0] = Bs[(t * 8 + tig) * 136 + bn];
                bf[j][1] = Bs[(t * 8 + tig + 4) * 136 + bn];
            }
#pragma unroll
            for (int i = 0; i < 4; i++)
#pragma unroll
                for (int j = 0; j < 8; j++)
                    mma_tf32_16x8x8(acc[i][j], af[i], bf[j]);
        }
        __syncthreads();
    }

    // Epilogue: bias add + store. c0/c1 are adjacent cols -> float2 stores.
#pragma unroll
    for (int i = 0; i < 4; i++) {
        const int row0 = m0 + wm * 64 + i * 16 + gid;
        const int row1 = row0 + 8;
        const float bb0 = bias[row0];
        const float bb1 = bias[row1];
#pragma unroll
        for (int j = 0; j < 8; j++) {
            const int col = w0 + wn * 64 + j * 8 + tig * 2;
            float2 o0, o1;
            o0.x = acc[i][j][0] + bb0; o0.y = acc[i][j][1] + bb0;
            o1.x = acc[i][j][2] + bb1; o1.y = acc[i][j][3] + bb1;
            *(float2*)&out[(size_t)row0 * 1024 + col] = o0;
            *(float2*)&out[(size_t)row1 * 1024 + col] = o1;
        }
    }
}

// ---------------------------------------------------------------------------
// Flash attention (unchanged, validated in R1): one CTA per (n, h, 64-q tile).
// ---------------------------------------------------------------------------
__global__ __launch_bounds__(256) void attn_kernel(
    const float* __restrict__ mask, float* __restrict__ out)
{
    const int qt = blockIdx.x;
    const int h  = blockIdx.y;
    const int n  = blockIdx.z;

    const int tid = threadIdx.x;
    const int tx  = tid & 15;
    const int ty  = tid >> 4;

    const size_t base = ((size_t)n * 1024 + (size_t)h * 64) * 1024;
    const float* Qh = g_q + base;
    const float* Kh = g_k + base;
    const float* Vh = g_v + base;
    const int q0 = qt * 64;

    __shared__ float Qs[64 * 64];
    __shared__ float KP[64 * 64];
    __shared__ float Vt[64 * 64];

#pragma unroll
    for (int it = 0; it < 4; it++) {
        int id = it * 256 + tid;
        int d = id >> 4, q4 = (id & 15) << 2;
        *(float4*)&Qs[d * 64 + q4] = *(const float4*)&Qh[(size_t)d * 1024 + q0 + q4];
    }

    float acc[4][4];
    float mrow[4], lrow[4];
#pragma unroll
    for (int i = 0; i < 4; i++) {
        mrow[i] = -1e30f; lrow[i] = 0.f;
#pragma unroll
        for (int j = 0; j < 4; j++) acc[i][j] = 0.f;
    }

    for (int k0 = 0; k0 < 1024; k0 += 64) {
        __syncthreads();
#pragma unroll
        for (int it = 0; it < 4; it++) {
            int id = it * 256 + tid;
            int d = id >> 4, k4 = id & 15;
            *(float4*)&KP[d * 64 + (k4 << 2)] =
                *(const float4*)&Kh[(size_t)d * 1024 + k0 + (k4 << 2)];
            float4 v = *(const float4*)&Vh[(size_t)d * 1024 + k0 + (k4 << 2)];
            int c = ((((d >> 2) ^ k4) << 2) | (d & 3));
            Vt[(k4 * 4 + 0) * 64 + c] = v.x;
            Vt[(k4 * 4 + 1) * 64 + c] = v.y;
            Vt[(k4 * 4 + 2) * 64 + c] = v.z;
            Vt[(k4 * 4 + 3) * 64 + c] = v.w;
        }
        float mk[4];
#pragma unroll
        for (int j = 0; j < 4; j++)
            mk[j] = mask[(size_t)n * 1024 + k0 + tx * 4 + j];
        __syncthreads();

        float s[4][4];
#pragma unroll
        for (int i = 0; i < 4; i++)
#pragma unroll
            for (int j = 0; j < 4; j++) s[i][j] = 0.f;
#pragma unroll
        for (int d = 0; d < 64; d++) {
            float qa[4], kb[4];
            *(float4*)qa = *(const float4*)&Qs[d * 64 + ty * 4];
            *(float4*)kb = *(const float4*)&KP[d * 64 + tx * 4];
#pragma unroll
            for (int i = 0; i < 4; i++)
#pragma unroll
                for (int j = 0; j < 4; j++)
                    s[i][j] += qa[i] * kb[j];
        }

#pragma unroll
        for (int i = 0; i < 4; i++) {
#pragma unroll
            for (int j = 0; j < 4; j++) s[i][j] = s[i][j] * 0.125f + mk[j];
            float mt = fmaxf(fmaxf(s[i][0], s[i][1]), fmaxf(s[i][2], s[i][3]));
#pragma unroll
            for (int off = 8; off >= 1; off >>= 1)
                mt = fmaxf(mt, __shfl_xor_sync(0xffffffffu, mt, off));
            float mnew = fmaxf(mrow[i], mt);
            float alpha = __expf(mrow[i] - mnew);
            float rs = 0.f;
#pragma unroll
            for (int j = 0; j < 4; j++) {
                s[i][j] = __expf(s[i][j] - mnew);
                rs += s[i][j];
            }
#pragma unroll
            for (int off = 8; off >= 1; off >>= 1)
                rs += __shfl_xor_sync(0xffffffffu, rs, off);
            lrow[i] = lrow[i] * alpha + rs;
            mrow[i] = mnew;
#pragma unroll
            for (int j = 0; j < 4; j++) acc[i][j] *= alpha;
        }

        __syncthreads();
#pragma unroll
        for (int i = 0; i < 4; i++) {
            float4 p4;
            p4.x = s[i][0]; p4.y = s[i][1]; p4.z = s[i][2]; p4.w = s[i][3];
            *(float4*)&KP[(ty * 4 + i) * 64 + tx * 4] = p4;
        }
        __syncthreads();

#pragma unroll
        for (int kk = 0; kk < 64; kk++) {
            float pa[4], vb[4];
#pragma unroll
            for (int i = 0; i < 4; i++) pa[i] = KP[(ty * 4 + i) * 64 + kk];
            *(float4*)vb = *(const float4*)&Vt[kk * 64 + ((tx ^ (kk >> 2)) << 2)];
#pragma unroll
            for (int i = 0; i < 4; i++)
#pragma unroll
                for (int j = 0; j < 4; j++)
                    acc[i][j] += pa[i] * vb[j];
        }
    }

    __syncthreads();
#pragma unroll
    for (int i = 0; i < 4; i++) {
        float inv = 1.f / lrow[i];
#pragma unroll
        for (int j = 0; j < 4; j++)
            Qs[(tx * 4 + j) * 64 + ty * 4 + i] = acc[i][j] * inv;
    }
    __syncthreads();
    float* Oh = out + base;
#pragma unroll
    for (int it = 0; it < 4; it++) {
        int id = it * 256 + tid;
        int d = id >> 4, q4 = (id & 15) << 2;
        *(float4*)&Oh[(size_t)d * 1024 + q0 + q4] = *(const float4*)&Qs[d * 64 + q4];
    }
}

extern "C" void kernel_launch(void* const* d_in, const int* in_sizes, int n_in,
                              void* d_out, int out_size)
{
    (void)in_sizes; (void)n_in; (void)out_size;
    const float* hs   = (const float*)d_in[0];
    const float* mask = (const float*)d_in[1];
    const float* wq   = (const float*)d_in[2];
    const float* bq   = (const float*)d_in[3];
    const float* wk   = (const float*)d_in[4];
    const float* bk   = (const float*)d_in[5];
    const float* wv   = (const float*)d_in[6];
    const float* bv   = (const float*)d_in[7];
    float* out = (float*)d_out;

    dim3 g1(8, 8, 24);   // (W/128, O/128, N*3)
    qkv_gemm_tc<<<g1, 128>>>(hs, wq, bq, wk, bk, wv, bv);

    dim3 g2(16, 16, 8);  // (W/64, H, N)
    attn_kernel<<<g2, 256>>>(mask, out);
}

// round 6
// speedup vs baseline: 3.0498x; 1.9181x over previous
#include <cuda_runtime.h>
#include <cstdint>
#include <math.h>

// Scratch for Q, K, V projections: [N=8, C=1024, W=1024] fp32 each.
__device__ float g_q[8u * 1024u * 1024u];
__device__ float g_k[8u * 1024u * 1024u];
__device__ float g_v[8u * 1024u * 1024u];

// fp32 -> tf32 (round to nearest) returning the b32 bit pattern
__device__ __forceinline__ uint32_t f2tf32(float f) {
    uint32_t u;
    asm("cvt.rna.tf32.f32 %0, %1;" : "=r"(u) : "f"(f));
    return u;
}
// fp32 -> tf32-rounded fp32 value
__device__ __forceinline__ float tf32r(float f) {
    return __uint_as_float(f2tf32(f));
}
__device__ __forceinline__ float ex2(float x) {
    float y;
    asm("ex2.approx.f32 %0, %1;" : "=f"(y) : "f"(x));
    return y;
}

// D(m16n8) += A(m16k8) * B(k8n8), tf32 inputs, fp32 accumulate
__device__ __forceinline__ void mma_tf32_16x8x8(
    float* d, const uint32_t* a, const uint32_t* b)
{
    asm volatile(
        "mma.sync.aligned.m16n8k8.row.col.f32.tf32.tf32.f32 "
        "{%0,%1,%2,%3}, {%4,%5,%6,%7}, {%8,%9}, {%0,%1,%2,%3};"
        : "+f"(d[0]), "+f"(d[1]), "+f"(d[2]), "+f"(d[3])
        : "r"(a[0]), "r"(a[1]), "r"(a[2]), "r"(a[3]),
          "r"(b[0]), "r"(b[1]));
}

// ---------------------------------------------------------------------------
// QKV projection on tensor cores (tf32 mma.sync) — unchanged from R5 (passed).
// ---------------------------------------------------------------------------
__global__ __launch_bounds__(128) void qkv_gemm_tc(
    const float* __restrict__ hs,
    const float* __restrict__ wq, const float* __restrict__ bq,
    const float* __restrict__ wk, const float* __restrict__ bk,
    const float* __restrict__ wv, const float* __restrict__ bv)
{
    __shared__ uint32_t As[128 * 20];
    __shared__ uint32_t Bs[16 * 136];

    const int which = blockIdx.z % 3;
    const int n     = blockIdx.z / 3;

    const float* A;
    const float* bias;
    float* out;
    if (which == 0)      { A = wq; bias = bq; out = g_q; }
    else if (which == 1) { A = wk; bias = bk; out = g_k; }
    else                 { A = wv; bias = bv; out = g_v; }

    const float* B = hs + (size_t)n * 1024u * 1024u;
    out += (size_t)n * 1024u * 1024u;

    const int m0 = blockIdx.y * 128;
    const int w0 = blockIdx.x * 128;

    const int tid = threadIdx.x;
    const int wid = tid >> 5;
    const int lane = tid & 31;
    const int gid = lane >> 2;
    const int tig = lane & 3;
    const int wm = wid >> 1;
    const int wn = wid & 1;

    const int a_r = tid >> 2;
    const int a_j = tid & 3;
    const int b_k = tid >> 5;
    const int b_n4 = tid & 31;

    const float* gA = A + (size_t)(m0 + a_r) * 1024 + a_j * 4;
    const float* gB = B + (size_t)b_k * 1024 + w0 + b_n4 * 4;

    float acc[4][8][4];
#pragma unroll
    for (int i = 0; i < 4; i++)
#pragma unroll
        for (int j = 0; j < 8; j++)
#pragma unroll
            for (int u = 0; u < 4; u++) acc[i][j][u] = 0.f;

    float4 areg[4], breg[4];
#pragma unroll
    for (int it = 0; it < 4; it++) {
        areg[it] = *(const float4*)(gA + (size_t)(it * 32) * 1024);
        breg[it] = *(const float4*)(gB + (size_t)(it * 4) * 1024);
    }

    for (int c = 0; c < 64; c++) {
#pragma unroll
        for (int it = 0; it < 4; it++) {
            uint4 ca;
            ca.x = f2tf32(areg[it].x); ca.y = f2tf32(areg[it].y);
            ca.z = f2tf32(areg[it].z); ca.w = f2tf32(areg[it].w);
            *(uint4*)&As[(a_r + it * 32) * 20 + a_j * 4] = ca;
            uint4 cb;
            cb.x = f2tf32(breg[it].x); cb.y = f2tf32(breg[it].y);
            cb.z = f2tf32(breg[it].z); cb.w = f2tf32(breg[it].w);
            *(uint4*)&Bs[(b_k + it * 4) * 136 + b_n4 * 4] = cb;
        }
        __syncthreads();

        if (c < 63) {
            const int k0 = (c + 1) * 16;
#pragma unroll
            for (int it = 0; it < 4; it++) {
                areg[it] = *(const float4*)(gA + (size_t)(it * 32) * 1024 + k0);
                breg[it] = *(const float4*)(gB + (size_t)(k0 + it * 4) * 1024);
            }
        }

#pragma unroll
        for (int t = 0; t < 2; t++) {
            uint32_t af[4][4];
#pragma unroll
            for (int i = 0; i < 4; i++) {
                const int bm = wm * 64 + i * 16;
                af[i][0] = As[(bm + gid) * 20 + t * 8 + tig];
                af[i][1] = As[(bm + gid + 8) * 20 + t * 8 + tig];
                af[i][2] = As[(bm + gid) * 20 + t * 8 + tig + 4];
                af[i][3] = As[(bm + gid + 8) * 20 + t * 8 + tig + 4];
            }
            uint32_t bf[8][2];
#pragma unroll
            for (int j = 0; j < 8; j++) {
                const int bn = wn * 64 + j * 8 + gid;
                bf[j][0] = Bs[(t * 8 + tig) * 136 + bn];
                bf[j][1] = Bs[(t * 8 + tig + 4) * 136 + bn];
            }
#pragma unroll
            for (int i = 0; i < 4; i++)
#pragma unroll
                for (int j = 0; j < 8; j++)
                    mma_tf32_16x8x8(acc[i][j], af[i], bf[j]);
        }
        __syncthreads();
    }

#pragma unroll
    for (int i = 0; i < 4; i++) {
        const int row0 = m0 + wm * 64 + i * 16 + gid;
        const int row1 = row0 + 8;
        const float bb0 = bias[row0];
        const float bb1 = bias[row1];
#pragma unroll
        for (int j = 0; j < 8; j++) {
            const int col = w0 + wn * 64 + j * 8 + tig * 2;
            float2 o0, o1;
            o0.x = acc[i][j][0] + bb0; o0.y = acc[i][j][1] + bb0;
            o1.x = acc[i][j][2] + bb1; o1.y = acc[i][j][3] + bb1;
            *(float2*)&out[(size_t)row0 * 1024 + col] = o0;
            *(float2*)&out[(size_t)row1 * 1024 + col] = o1;
        }
    }
}

// ---------------------------------------------------------------------------
// Tensor-core flash attention.
// CTA per (n, h, 64-query tile); 128 threads = 4 warps, warp = 16 q-rows.
// S = Q^T K via mma (A = Q frags in regs, B = K smem [d][k] stride 72).
// PV via mma (A = P from shfl-converted acc frags, B = V smem [d][k] stride 68).
// Online softmax in accumulator layout; P tf32-rounded before row-sum so the
// PV weighting self-normalizes.
// grid: (16 qtiles, 16 h, 8 n)
// ---------------------------------------------------------------------------
__global__ __launch_bounds__(128, 3) void attn_tc(
    const float* __restrict__ mask, float* __restrict__ out)
{
    __shared__ uint32_t Ks[64 * 72];   // 18.0 KB, [d][k], conflict-free frags
    __shared__ uint32_t Vs[64 * 68];   // 17.0 KB, [d][k], conflict-free frags

    const int qt = blockIdx.x;
    const int h  = blockIdx.y;
    const int n  = blockIdx.z;

    const int tid  = threadIdx.x;
    const int wm   = tid >> 5;
    const int lane = tid & 31;
    const int gid  = lane >> 2;
    const int tig  = lane & 3;

    const size_t base = ((size_t)n * 1024 + (size_t)h * 64) * 1024;
    const float* Qg = g_q + base;
    const float* Kg = g_k + base;
    const float* Vg = g_v + base;
    const int qrow = qt * 64 + wm * 16 + gid;

    // Q fragments: reused across all 16 k-tiles. qa[t] covers d = 8t..8t+7.
    uint32_t qa[8][4];
#pragma unroll
    for (int t = 0; t < 8; t++) {
        qa[t][0] = f2tf32(Qg[(size_t)(8 * t + tig) * 1024 + qrow]);
        qa[t][1] = f2tf32(Qg[(size_t)(8 * t + tig) * 1024 + qrow + 8]);
        qa[t][2] = f2tf32(Qg[(size_t)(8 * t + tig + 4) * 1024 + qrow]);
        qa[t][3] = f2tf32(Qg[(size_t)(8 * t + tig + 4) * 1024 + qrow + 8]);
    }

    float o[8][4];
#pragma unroll
    for (int jn = 0; jn < 8; jn++)
#pragma unroll
        for (int u = 0; u < 4; u++) o[jn][u] = 0.f;
    float m0 = -1e30f, m1 = -1e30f, l0 = 0.f, l1 = 0.f;

    const int ld_d  = tid >> 4;   // 0..7 ; rows d = ld_d + 8*i
    const int ld_k4 = tid & 15;
    const float L2E = 1.44269504f;

    for (int kt = 0; kt < 16; kt++) {
        const int k0 = kt * 64;
        __syncthreads();
        // Load K and V tiles (64d x 64k) with tf32 rounding
#pragma unroll
        for (int i = 0; i < 8; i++) {
            const int d = i * 8 + ld_d;
            float4 kv = *(const float4*)&Kg[(size_t)d * 1024 + k0 + ld_k4 * 4];
            uint4 ku;
            ku.x = f2tf32(kv.x); ku.y = f2tf32(kv.y);
            ku.z = f2tf32(kv.z); ku.w = f2tf32(kv.w);
            *(uint4*)&Ks[d * 72 + ld_k4 * 4] = ku;
            float4 vv = *(const float4*)&Vg[(size_t)d * 1024 + k0 + ld_k4 * 4];
            uint4 vu;
            vu.x = f2tf32(vv.x); vu.y = f2tf32(vv.y);
            vu.z = f2tf32(vv.z); vu.w = f2tf32(vv.w);
            *(uint4*)&Vs[d * 68 + ld_k4 * 4] = vu;
        }
        __syncthreads();

        // S = Q^T K : s[j] covers k-cols 8j..8j+7
        float s[8][4];
#pragma unroll
        for (int j = 0; j < 8; j++)
#pragma unroll
            for (int u = 0; u < 4; u++) s[j][u] = 0.f;
#pragma unroll
        for (int t = 0; t < 8; t++) {
#pragma unroll
            for (int j = 0; j < 8; j++) {
                uint32_t b[2];
                b[0] = Ks[(8 * t + tig) * 72 + 8 * j + gid];
                b[1] = Ks[(8 * t + tig + 4) * 72 + 8 * j + gid];
                mma_tf32_16x8x8(s[j], qa[t], b);
            }
        }

        // scale + mask + online softmax (row0 = qrow, row1 = qrow+8)
        float mx0 = -1e30f, mx1 = -1e30f;
#pragma unroll
        for (int j = 0; j < 8; j++) {
            float2 mv = *(const float2*)&mask[(size_t)n * 1024 + k0 + 8 * j + 2 * tig];
            s[j][0] = fmaf(s[j][0], 0.125f, mv.x);
            s[j][1] = fmaf(s[j][1], 0.125f, mv.y);
            s[j][2] = fmaf(s[j][2], 0.125f, mv.x);
            s[j][3] = fmaf(s[j][3], 0.125f, mv.y);
            mx0 = fmaxf(mx0, fmaxf(s[j][0], s[j][1]));
            mx1 = fmaxf(mx1, fmaxf(s[j][2], s[j][3]));
        }
        mx0 = fmaxf(mx0, __shfl_xor_sync(0xffffffffu, mx0, 1));
        mx0 = fmaxf(mx0, __shfl_xor_sync(0xffffffffu, mx0, 2));
        mx1 = fmaxf(mx1, __shfl_xor_sync(0xffffffffu, mx1, 1));
        mx1 = fmaxf(mx1, __shfl_xor_sync(0xffffffffu, mx1, 2));
        const float nm0 = fmaxf(m0, mx0);
        const float nm1 = fmaxf(m1, mx1);
        const float a0 = ex2((m0 - nm0) * L2E);
        const float a1 = ex2((m1 - nm1) * L2E);
        const float c0 = -nm0 * L2E;
        const float c1 = -nm1 * L2E;
        float s0 = 0.f, s1 = 0.f;
#pragma unroll
        for (int j = 0; j < 8; j++) {
            s[j][0] = tf32r(ex2(fmaf(s[j][0], L2E, c0)));
            s[j][1] = tf32r(ex2(fmaf(s[j][1], L2E, c0)));
            s[j][2] = tf32r(ex2(fmaf(s[j][2], L2E, c1)));
            s[j][3] = tf32r(ex2(fmaf(s[j][3], L2E, c1)));
            s0 += s[j][0] + s[j][1];
            s1 += s[j][2] + s[j][3];
        }
        s0 += __shfl_xor_sync(0xffffffffu, s0, 1);
        s0 += __shfl_xor_sync(0xffffffffu, s0, 2);
        s1 += __shfl_xor_sync(0xffffffffu, s1, 1);
        s1 += __shfl_xor_sync(0xffffffffu, s1, 2);
        l0 = l0 * a0 + s0;
        l1 = l1 * a1 + s1;
        m0 = nm0; m1 = nm1;
#pragma unroll
        for (int jn = 0; jn < 8; jn++) {
            o[jn][0] *= a0; o[jn][1] *= a0;
            o[jn][2] *= a1; o[jn][3] *= a1;
        }

        // PV: ctx += P * V. A-frag for k-chunk t built from P tile j=t via shfl.
        const int src0 = (lane & 28) | (tig >> 1);
        const int src1 = src0 + 2;
#pragma unroll
        for (int t = 0; t < 8; t++) {
            float x00 = __shfl_sync(0xffffffffu, s[t][0], src0);
            float x01 = __shfl_sync(0xffffffffu, s[t][1], src0);
            float x10 = __shfl_sync(0xffffffffu, s[t][2], src0);
            float x11 = __shfl_sync(0xffffffffu, s[t][3], src0);
            float x20 = __shfl_sync(0xffffffffu, s[t][0], src1);
            float x21 = __shfl_sync(0xffffffffu, s[t][1], src1);
            float x30 = __shfl_sync(0xffffffffu, s[t][2], src1);
            float x31 = __shfl_sync(0xffffffffu, s[t][3], src1);
            uint32_t a[4];
            a[0] = __float_as_uint((tig & 1) ? x01 : x00);
            a[1] = __float_as_uint((tig & 1) ? x11 : x10);
            a[2] = __float_as_uint((tig & 1) ? x21 : x20);
            a[3] = __float_as_uint((tig & 1) ? x31 : x30);
#pragma unroll
            for (int jn = 0; jn < 8; jn++) {
                uint32_t b[2];
                b[0] = Vs[(8 * jn + gid) * 68 + 8 * t + tig];
                b[1] = Vs[(8 * jn + gid) * 68 + 8 * t + tig + 4];
                mma_tf32_16x8x8(o[jn], a, b);
            }
        }
    }

    // Epilogue: normalize + store transposed (out[d][q])
    const float inv0 = 1.f / l0;
    const float inv1 = 1.f / l1;
    float* Og = out + base;
#pragma unroll
    for (int jn = 0; jn < 8; jn++) {
        const int d0 = 8 * jn + 2 * tig;
        Og[(size_t)d0 * 1024 + qrow]           = o[jn][0] * inv0;
        Og[(size_t)(d0 + 1) * 1024 + qrow]     = o[jn][1] * inv0;
        Og[(size_t)d0 * 1024 + qrow + 8]       = o[jn][2] * inv1;
        Og[(size_t)(d0 + 1) * 1024 + qrow + 8] = o[jn][3] * inv1;
    }
}

extern "C" void kernel_launch(void* const* d_in, const int* in_sizes, int n_in,
                              void* d_out, int out_size)
{
    (void)in_sizes; (void)n_in; (void)out_size;
    const float* hs   = (const float*)d_in[0];
    const float* mask = (const float*)d_in[1];
    const float* wq   = (const float*)d_in[2];
    const float* bq   = (const float*)d_in[3];
    const float* wk   = (const float*)d_in[4];
    const float* bk   = (const float*)d_in[5];
    const float* wv   = (const float*)d_in[6];
    const float* bv   = (const float*)d_in[7];
    float* out = (float*)d_out;

    dim3 g1(8, 8, 24);   // (W/128, O/128, N*3)
    qkv_gemm_tc<<<g1, 128>>>(hs, wq, bq, wk, bk, wv, bv);

    dim3 g2(16, 16, 8);  // (W/64, H, N)
    attn_tc<<<g2, 128>>>(mask, out);
}